// round 16
// baseline (speedup 1.0000x reference)
#include <cuda_runtime.h>
#include <cuda_fp16.h>
#include <cstdint>
#include <cstddef>

// Problem constants (fixed by the benchmark)
//  x: (16, 64, 64, 512)  -> 65536 tokens x 512 ch
//  w_qkv: (512, 1536), b_qkv: (1536)
//  rel_pos: (225, 16)
//  w_out: (512, 512), b_out: (512)
//  window 8x8, shift 4, 16 heads, head_dim 32

#define M_TOK   65536
#define KDIM    512
#define N_QKV   1536
#define N_OUT   512
#define NHEADS  16

// Scratch (allocation-free rule: __device__ globals)
static __device__ __half g_xh  [(size_t)M_TOK * KDIM];    // 64 MB  (x as fp16)
static __device__ __half g_qkvh[(size_t)M_TOK * N_QKV];   // 192 MB
static __device__ __half g_atth[(size_t)M_TOK * N_OUT];   // 64 MB
static __device__ __half g_btqh[(size_t)N_QKV * KDIM];    // 1.5 MB (w_qkv^T fp16)
static __device__ __half g_btoh[(size_t)N_OUT * KDIM];    // 0.5 MB (w_out^T fp16)

// pack two floats into f16x2 (lo in low 16 bits)
__device__ __forceinline__ uint32_t pack_h2(float lo, float hi) {
    uint32_t r;
    asm("cvt.rn.f16x2.f32 %0, %1, %2;" : "=r"(r) : "f"(hi), "f"(lo));
    return r;
}

__device__ __forceinline__ uint32_t smem_u32(const void* p) {
    uint32_t a;
    asm("{ .reg .u64 t; cvta.to.shared.u64 t, %1; cvt.u32.u64 %0, t; }" : "=r"(a) : "l"(p));
    return a;
}

__device__ __forceinline__ void mma_f16(float* d, const uint32_t* a, const uint32_t* b) {
    asm volatile(
        "mma.sync.aligned.m16n8k16.row.col.f32.f16.f16.f32 "
        "{%0,%1,%2,%3}, {%4,%5,%6,%7}, {%8,%9}, {%0,%1,%2,%3};\n"
        : "+f"(d[0]), "+f"(d[1]), "+f"(d[2]), "+f"(d[3])
        : "r"(a[0]), "r"(a[1]), "r"(a[2]), "r"(a[3]),
          "r"(b[0]), "r"(b[1]));
}

__device__ __forceinline__ void ldsm_x4(uint32_t* r, uint32_t saddr) {
    asm volatile("ldmatrix.sync.aligned.m8n8.x4.shared.b16 {%0,%1,%2,%3}, [%4];"
                 : "=r"(r[0]), "=r"(r[1]), "=r"(r[2]), "=r"(r[3]) : "r"(saddr));
}
__device__ __forceinline__ void ldsm_x4_t(uint32_t* r, uint32_t saddr) {
    asm volatile("ldmatrix.sync.aligned.m8n8.x4.trans.shared.b16 {%0,%1,%2,%3}, [%4];"
                 : "=r"(r[0]), "=r"(r[1]), "=r"(r[2]), "=r"(r[3]) : "r"(saddr));
}

__device__ __forceinline__ void cp_async16(uint32_t dst, const void* src) {
    asm volatile("cp.async.cg.shared.global [%0], [%1], 16;\n" :: "r"(dst), "l"(src));
}
__device__ __forceinline__ void cp_commit() {
    asm volatile("cp.async.commit_group;\n" ::: "memory");
}
template <int N>
__device__ __forceinline__ void cp_wait() {
    asm volatile("cp.async.wait_group %0;\n" :: "n"(N) : "memory");
}

// ---------------------------------------------------------------------------
// fp32 -> fp16 bulk convert (8 elems / thread)
// ---------------------------------------------------------------------------
__global__ __launch_bounds__(256)
void f2h_kernel(const float* __restrict__ in, __half* __restrict__ out, size_t n8) {
    const size_t i = (size_t)blockIdx.x * blockDim.x + threadIdx.x;
    if (i >= n8) return;
    const float4* p = (const float4*)in + i * 2;
    float4 a = __ldg(p), b = __ldg(p + 1);
    uint4 o;
    o.x = pack_h2(a.x, a.y);  o.y = pack_h2(a.z, a.w);
    o.z = pack_h2(b.x, b.y);  o.w = pack_h2(b.z, b.w);
    *((uint4*)out + i) = o;
}

// ---------------------------------------------------------------------------
// Weight transpose + fp16: out[c][r] = (half)in[r][c].  R, C multiples of 32.
// ---------------------------------------------------------------------------
__global__ void transpose_h_kernel(const float* __restrict__ in, __half* __restrict__ out,
                                   int R, int C) {
    __shared__ float t[32][33];
    const int c0 = blockIdx.x * 32, r0 = blockIdx.y * 32;
    const int x = threadIdx.x, y = threadIdx.y;
    #pragma unroll
    for (int dy = 0; dy < 32; dy += 8)
        t[y + dy][x] = in[(size_t)(r0 + y + dy) * C + c0 + x];
    __syncthreads();
    #pragma unroll
    for (int dy = 0; dy < 32; dy += 8)
        out[(size_t)(c0 + y + dy) * R + r0 + x] = __float2half(t[x][y + dy]);
}

// ---------------------------------------------------------------------------
// Dense GEMM: C[M,N] = A[M,K]*B[K,N] + bias[N]; A, Bt fp16 (Bt = B^T, K-major),
// fp16 mma.sync m16n8k16 (fp32 accum).
// BM=128, BN=128, BK=32, 128 threads = 4 warps, warp tile 64x64 (2x2 grid).
// 5-stage cp.async.cg pipeline (dynamic smem, ~2048cyc prefetch slack),
// one syncthreads/tile.
// Smem rows: 32 fp16 = 64 B = 4 x 16B chunks, XOR swizzle c^((row>>1)&3).
// CT = half (packed h2 stores) or float.
// ---------------------------------------------------------------------------
#define GSTAGES     5
#define STAGE_BYTES 16384
#define GEMM_SMEM   (GSTAGES * STAGE_BYTES)   // 80 KB dynamic

template <typename CT>
__global__ __launch_bounds__(128, 2)
void gemm_h_kernel(const __half* __restrict__ A, const __half* __restrict__ Bt,
                   const float* __restrict__ bias, CT* __restrict__ C,
                   int N, int K)
{
    extern __shared__ __align__(16) char sS[];  // per stage: A[0,8K), B[8K,16K)

    const int tid  = threadIdx.x;
    const int lane = tid & 31;
    const int warp = tid >> 5;
    const int g    = lane >> 2;
    const int tig  = lane & 3;
    const int bm   = blockIdx.y * 128;
    const int bn   = blockIdx.x * 128;
    const int m0   = (warp >> 1) * 64;
    const int n0   = (warp & 1) * 64;

    // loader: thread -> rows lr+32j (j=0..3), 16B chunk lc; key invariant in j
    const int lr = tid >> 2;          // 0..31
    const int lc = tid & 3;
    const uint32_t sco = (uint32_t)(((lc ^ ((lr >> 1) & 3))) << 4);
    uint32_t soff[4];
    #pragma unroll
    for (int j = 0; j < 4; j++) soff[j] = (uint32_t)((lr + 32 * j) * 64) + sco;
    const __half* Ag = A  + (size_t)(bm + lr) * K + lc * 8;
    const __half* Bg = Bt + (size_t)(bn + lr) * K + lc * 8;
    const int rowStrideA = 32 * K;

    const uint32_t sBase = smem_u32(sS);

    // fragment ldmatrix addresses (byte offsets within a stage)
    const int r8 = lane & 7;
    uint32_t aoff[4], boff[4];
    #pragma unroll
    for (int mt = 0; mt < 4; mt++) {
        const int m = m0 + mt * 16 + r8 + ((lane >> 3) & 1) * 8;
        const int c = lane >> 4;
        aoff[mt] = (uint32_t)(m * 64 + ((c ^ ((m >> 1) & 3)) << 4));
    }
    #pragma unroll
    for (int nb = 0; nb < 4; nb++) {
        const int n = n0 + nb * 16 + r8 + (lane >> 4) * 8;
        const int c = (lane >> 3) & 1;
        boff[nb] = (uint32_t)(8192 + n * 64 + ((c ^ ((n >> 1) & 3)) << 4));
    }

    float acc[4][8][4];
    #pragma unroll
    for (int a = 0; a < 4; a++)
        #pragma unroll
        for (int b = 0; b < 8; b++)
            #pragma unroll
            for (int c = 0; c < 4; c++) acc[a][b][c] = 0.f;

    const int T = K >> 5;   // BK = 32

    // prologue: prefetch tiles 0..GSTAGES-2
    #pragma unroll
    for (int p = 0; p < GSTAGES - 1; p++) {
        const uint32_t sb = sBase + p * STAGE_BYTES;
        const __half* a = Ag + p * 32;
        const __half* b = Bg + p * 32;
        #pragma unroll
        for (int j = 0; j < 4; j++) {
            cp_async16(sb + soff[j],        a + j * rowStrideA);
            cp_async16(sb + 8192 + soff[j], b + j * rowStrideA);
        }
        cp_commit();
    }

    for (int t = 0; t < T; t++) {
        cp_wait<GSTAGES - 2>();
        __syncthreads();

        // prefetch tile t+GSTAGES-1 into the stage just freed
        if (t + GSTAGES - 1 < T) {
            const int st = (t + GSTAGES - 1) % GSTAGES;
            const uint32_t sb = sBase + st * STAGE_BYTES;
            const __half* a = Ag + (t + GSTAGES - 1) * 32;
            const __half* b = Bg + (t + GSTAGES - 1) * 32;
            #pragma unroll
            for (int j = 0; j < 4; j++) {
                cp_async16(sb + soff[j],        a + j * rowStrideA);
                cp_async16(sb + 8192 + soff[j], b + j * rowStrideA);
            }
        }
        cp_commit();

        const uint32_t sb = sBase + (t % GSTAGES) * STAGE_BYTES;
        #pragma unroll
        for (int s = 0; s < 2; s++) {
            const uint32_t sx = (uint32_t)(s << 5);   // chunk +2 == XOR 32 bytes
            uint32_t afr[4][4], bfr[4][4];
            #pragma unroll
            for (int mt = 0; mt < 4; mt++)
                ldsm_x4(afr[mt], sb + (aoff[mt] ^ sx));
            #pragma unroll
            for (int nb = 0; nb < 4; nb++)
                ldsm_x4(bfr[nb], sb + (boff[nb] ^ sx));
            #pragma unroll
            for (int mt = 0; mt < 4; mt++)
                #pragma unroll
                for (int nb = 0; nb < 4; nb++) {
                    mma_f16(acc[mt][nb * 2],     afr[mt], &bfr[nb][0]);
                    mma_f16(acc[mt][nb * 2 + 1], afr[mt], &bfr[nb][2]);
                }
        }
    }

    // Epilogue: bias + store
    #pragma unroll
    for (int mt = 0; mt < 4; mt++) {
        #pragma unroll
        for (int nt = 0; nt < 8; nt++) {
            const int row0 = bm + m0 + mt * 16 + g;
            const int col0 = bn + n0 + nt * 8 + tig * 2;
            const float b0 = __ldg(bias + col0);
            const float b1 = __ldg(bias + col0 + 1);
            if constexpr (sizeof(CT) == 2) {
                *(uint32_t*)((__half*)C + (size_t)row0 * N + col0) =
                    pack_h2(acc[mt][nt][0] + b0, acc[mt][nt][1] + b1);
                *(uint32_t*)((__half*)C + (size_t)(row0 + 8) * N + col0) =
                    pack_h2(acc[mt][nt][2] + b0, acc[mt][nt][3] + b1);
            } else {
                float2 r0, r1;
                r0.x = acc[mt][nt][0] + b0; r0.y = acc[mt][nt][1] + b1;
                r1.x = acc[mt][nt][2] + b0; r1.y = acc[mt][nt][3] + b1;
                *(float2*)((float*)C + (size_t)row0 * N + col0)       = r0;
                *(float2*)((float*)C + (size_t)(row0 + 8) * N + col0) = r1;
            }
        }
    }
}

// ---------------------------------------------------------------------------
// Windowed attention, full fp16 mma.sync (unchanged from R14/R15).
// Block = (head, window), 128 threads = 4 warps, warp w owns query rows
// [16w, 16w+16). S = Q*K^T (k16 x2), softmax in accumulator layout (scale
// folded into bias FFMA), P packed to fp16 smem, O = P*V with V consumed in
// natural (key-major) layout via ldmatrix.trans.
//   pixel(h) = (wh*8 + ph + 4) & 63   (same for w)
// ---------------------------------------------------------------------------
__device__ __forceinline__ int pix_row(int win, int t) {
    const int b  = win >> 6;
    const int wi = win & 63;
    const int h  = (((wi >> 3) << 3) + (t >> 3) + 4) & 63;
    const int w  = (((wi & 7) << 3) + (t & 7) + 4) & 63;
    return (((b << 6) | h) << 6) | w;   // b*4096 + h*64 + w
}

__global__ __launch_bounds__(128)
void attn_h_kernel(const __half* __restrict__ qkv, const float* __restrict__ rel_pos,
                   __half* __restrict__ att)
{
    const int head = blockIdx.x;
    const int win  = blockIdx.y;
    const int tid  = threadIdx.x;
    const int lane = tid & 31;
    const int g    = lane >> 2;
    const int tig  = lane & 3;
    const int m0   = (tid >> 5) * 16;

    __shared__ __align__(16) char sQ[4096];
    __shared__ __align__(16) char sK[4096];
    __shared__ __align__(16) char sV[4096];
    __shared__ __align__(16) char sP[8192];
    __shared__ float rp[225];

    const uint32_t qB = smem_u32(sQ);
    const uint32_t kB = smem_u32(sK);
    const uint32_t vB = smem_u32(sV);
    const uint32_t pB = smem_u32(sP);

    for (int i = tid; i < 225; i += 128) rp[i] = __ldg(rel_pos + i * NHEADS + head);
    {
        const int row  = tid >> 1;
        const int half = tid & 1;
        const size_t base = (size_t)pix_row(win, row) * N_QKV + head * 32;
        const uint4* qp = (const uint4*)(qkv + base);
        const uint4* kp = (const uint4*)(qkv + base + 512);
        const uint4* vp = (const uint4*)(qkv + base + 1024);
        const int key = (row >> 1) & 3;
        #pragma unroll
        for (int u = 0; u < 2; u++) {
            const int c = half * 2 + u;
            const uint32_t sw = (uint32_t)(row * 64 + ((c ^ key) << 4));
            *(uint4*)(sQ + sw) = __ldg(qp + c);
            *(uint4*)(sK + sw) = __ldg(kp + c);
            *(uint4*)(sV + sw) = __ldg(vp + c);
        }
    }
    __syncthreads();

    const int r8 = lane & 7;
    uint32_t aoffQ, boffK[4];
    {
        const int m = m0 + r8 + ((lane >> 3) & 1) * 8;
        const int c = lane >> 4;
        aoffQ = (uint32_t)(m * 64 + ((c ^ ((m >> 1) & 3)) << 4));
    }
    #pragma unroll
    for (int nb = 0; nb < 4; nb++) {
        const int n = nb * 16 + r8 + (lane >> 4) * 8;
        const int c = (lane >> 3) & 1;
        boffK[nb] = (uint32_t)(n * 64 + ((c ^ ((n >> 1) & 3)) << 4));
    }

    float acc[8][4];
    #pragma unroll
    for (int nt = 0; nt < 8; nt++)
        #pragma unroll
        for (int c = 0; c < 4; c++) acc[nt][c] = 0.f;

    #pragma unroll
    for (int kt = 0; kt < 2; kt++) {
        const uint32_t sx = (uint32_t)(kt << 5);
        uint32_t a[4];
        ldsm_x4(a, qB + (aoffQ ^ sx));
        #pragma unroll
        for (int nb = 0; nb < 4; nb++) {
            uint32_t b[4];
            ldsm_x4(b, kB + (boffK[nb] ^ sx));
            mma_f16(acc[nb * 2],     a, b);
            mma_f16(acc[nb * 2 + 1], a, b + 2);
        }
    }

    const float scale = 0.17677669529663687f;   // 1/sqrt(32)
    const int i0 = m0 + g;
    const int yi = i0 >> 3, xi = i0 & 7;
    float mx0 = -1e30f, mx1 = -1e30f;
    #pragma unroll
    for (int nt = 0; nt < 8; nt++) {
        const int bi = (yi - nt + 7) * 15 + (xi - 2 * tig + 7);
        acc[nt][0] = fmaf(acc[nt][0], scale, rp[bi]);
        acc[nt][1] = fmaf(acc[nt][1], scale, rp[bi - 1]);
        acc[nt][2] = fmaf(acc[nt][2], scale, rp[bi + 15]);
        acc[nt][3] = fmaf(acc[nt][3], scale, rp[bi + 14]);
        mx0 = fmaxf(mx0, fmaxf(acc[nt][0], acc[nt][1]));
        mx1 = fmaxf(mx1, fmaxf(acc[nt][2], acc[nt][3]));
    }
    mx0 = fmaxf(mx0, __shfl_xor_sync(0xffffffffu, mx0, 1));
    mx0 = fmaxf(mx0, __shfl_xor_sync(0xffffffffu, mx0, 2));
    mx1 = fmaxf(mx1, __shfl_xor_sync(0xffffffffu, mx1, 1));
    mx1 = fmaxf(mx1, __shfl_xor_sync(0xffffffffu, mx1, 2));

    float s0 = 0.f, s1 = 0.f;
    #pragma unroll
    for (int nt = 0; nt < 8; nt++) {
        acc[nt][0] = __expf(acc[nt][0] - mx0);
        acc[nt][1] = __expf(acc[nt][1] - mx0);
        acc[nt][2] = __expf(acc[nt][2] - mx1);
        acc[nt][3] = __expf(acc[nt][3] - mx1);
        s0 += acc[nt][0] + acc[nt][1];
        s1 += acc[nt][2] + acc[nt][3];
    }
    s0 += __shfl_xor_sync(0xffffffffu, s0, 1);
    s0 += __shfl_xor_sync(0xffffffffu, s0, 2);
    s1 += __shfl_xor_sync(0xffffffffu, s1, 1);
    s1 += __shfl_xor_sync(0xffffffffu, s1, 2);
    const float inv0 = 1.0f / s0;
    const float inv1 = 1.0f / s1;

    {
        const int keyP = i0 & 7;
        #pragma unroll
        for (int nt = 0; nt < 8; nt++) {
            const uint32_t a0 = (uint32_t)(i0 * 128       + ((nt ^ keyP) << 4) + 4 * tig);
            const uint32_t a1 = (uint32_t)((i0 + 8) * 128 + ((nt ^ keyP) << 4) + 4 * tig);
            *(uint32_t*)(sP + a0) = pack_h2(acc[nt][0] * inv0, acc[nt][1] * inv0);
            *(uint32_t*)(sP + a1) = pack_h2(acc[nt][2] * inv1, acc[nt][3] * inv1);
        }
    }
    __syncwarp();

    float accO[4][4];
    #pragma unroll
    for (int nt = 0; nt < 4; nt++)
        #pragma unroll
        for (int c = 0; c < 4; c++) accO[nt][c] = 0.f;

    uint32_t aoffP;
    {
        const int m = m0 + r8 + ((lane >> 3) & 1) * 8;
        const int c = lane >> 4;
        aoffP = (uint32_t)(m * 128 + ((c ^ (m & 7)) << 4));
    }
    uint32_t voff[2];
    {
        const int rb  = r8 + ((lane >> 3) & 1) * 8;
        const int key = (rb >> 1) & 3;
        #pragma unroll
        for (int nb = 0; nb < 2; nb++) {
            const int c = nb * 2 + (lane >> 4);
            voff[nb] = (uint32_t)(rb * 64 + ((c ^ key) << 4));
        }
    }

    #pragma unroll
    for (int kt = 0; kt < 4; kt++) {
        uint32_t a[4];
        ldsm_x4(a, pB + (aoffP ^ ((uint32_t)kt << 5)));
        #pragma unroll
        for (int nb = 0; nb < 2; nb++) {
            uint32_t b[4];
            ldsm_x4_t(b, vB + voff[nb] + (uint32_t)kt * 1024);
            mma_f16(accO[nb * 2],     a, b);
            mma_f16(accO[nb * 2 + 1], a, b + 2);
        }
    }

    {
        const size_t r0 = (size_t)pix_row(win, i0)     * N_OUT + head * 32;
        const size_t r1 = (size_t)pix_row(win, i0 + 8) * N_OUT + head * 32;
        #pragma unroll
        for (int nt = 0; nt < 4; nt++) {
            *(uint32_t*)(att + r0 + nt * 8 + 2 * tig) = pack_h2(accO[nt][0], accO[nt][1]);
            *(uint32_t*)(att + r1 + nt * 8 + 2 * tig) = pack_h2(accO[nt][2], accO[nt][3]);
        }
    }
}

// ---------------------------------------------------------------------------
extern "C" void kernel_launch(void* const* d_in, const int* in_sizes, int n_in,
                              void* d_out, int out_size)
{
    const float* x       = (const float*)d_in[0];
    const float* w_qkv   = (const float*)d_in[1];
    const float* b_qkv   = (const float*)d_in[2];
    const float* rel_pos = (const float*)d_in[3];
    const float* w_out   = (const float*)d_in[4];
    const float* b_out   = (const float*)d_in[5];
    float* out = (float*)d_out;

    __half *xh, *qkvh, *atth, *btqh, *btoh;
    cudaGetSymbolAddress((void**)&xh,   g_xh);
    cudaGetSymbolAddress((void**)&qkvh, g_qkvh);
    cudaGetSymbolAddress((void**)&atth, g_atth);
    cudaGetSymbolAddress((void**)&btqh, g_btqh);
    cudaGetSymbolAddress((void**)&btoh, g_btoh);

    static bool attr_set = false;
    if (!attr_set) {
        cudaFuncSetAttribute(gemm_h_kernel<__half>,
                             cudaFuncAttributeMaxDynamicSharedMemorySize, GEMM_SMEM);
        cudaFuncSetAttribute(gemm_h_kernel<float>,
                             cudaFuncAttributeMaxDynamicSharedMemorySize, GEMM_SMEM);
        attr_set = true;
    }

    // 0) convert inputs to fp16 once per launch
    {
        const size_t n8 = (size_t)M_TOK * KDIM / 8;
        f2h_kernel<<<(unsigned)((n8 + 255) / 256), 256>>>(x, xh, n8);
    }
    transpose_h_kernel<<<dim3(N_QKV / 32, KDIM / 32), dim3(32, 8)>>>(w_qkv, btqh, KDIM, N_QKV);
    transpose_h_kernel<<<dim3(N_OUT / 32, KDIM / 32), dim3(32, 8)>>>(w_out, btoh, KDIM, N_OUT);

    // 1) QKV projection (fp16 in/out)
    gemm_h_kernel<__half><<<dim3(N_QKV / 128, M_TOK / 128), 128, GEMM_SMEM>>>(
        xh, btqh, b_qkv, qkvh, N_QKV, KDIM);

    // 2) Shifted-window attention (fp16 in/out)
    attn_h_kernel<<<dim3(NHEADS, 1024), dim3(128)>>>(qkvh, rel_pos, atth);

    // 3) Output projection (fp16 in, fp32 out)
    gemm_h_kernel<float><<<dim3(N_OUT / 128, M_TOK / 128), 128, GEMM_SMEM>>>(
        atth, btoh, b_out, out, N_OUT, KDIM);
}